// round 11
// baseline (speedup 1.0000x reference)
#include <cuda_runtime.h>
#include <cstdint>

// UltraTinyGRU, warp-specialized producer/consumer.
// B=4096, T=512, F=16, H=4. 128 blocks x 256 threads.
// Warps 0-3: scan (recurrence chain only). Warps 4-7: producers
// (cp.async x staging + packed f32x2 input-gate dots -> smem gate buffer).
// Warp w pairs with warp w+4 on the same SMSP (wid%4): the producer issues
// dot work inside the scan warp's tanh/shfl stall windows.
// Handoff: double-buffered gate smem + pairwise named barriers (64 threads).
// R11 fix vs R10: final produce() must use cp.async.wait_group 0 — at the
// tail the needed x-stage is the NEWEST pending group, so wait_group 1
// never waited for it (stale gates on the last timestep, rel_err 3e-3).

#define GT 512
#define ROWS 32
#define THREADS 256
#define SSTEPS 4
#define NSTAGE (GT / SSTEPS)   // 128
#define XBUFS 3

__device__ __forceinline__ void cp_async16(void* smem_dst, const void* gmem_src) {
    unsigned int s = (unsigned int)__cvta_generic_to_shared(smem_dst);
    asm volatile("cp.async.cg.shared.global [%0], [%1], 16;\n"
                 :: "r"(s), "l"(gmem_src) : "memory");
}
__device__ __forceinline__ void cp_async_commit() {
    asm volatile("cp.async.commit_group;\n" ::: "memory");
}

__device__ __forceinline__ float tanh_fast(float x) {
    float y;
    asm("tanh.approx.f32 %0, %1;" : "=f"(y) : "f"(x));
    return y;
}

// ---- packed fp32x2 helpers ----
__device__ __forceinline__ double pack2(float lo, float hi) {
    double d;
    asm("mov.b64 %0, {%1, %2};" : "=d"(d) : "f"(lo), "f"(hi));
    return d;
}
__device__ __forceinline__ double fma2(double a, double b, double c) {
    double d;
    asm("fma.rn.f32x2 %0, %1, %2, %3;" : "=d"(d) : "d"(a), "d"(b), "d"(c));
    return d;
}
__device__ __forceinline__ double mul2(double a, double b) {
    double d;
    asm("mul.rn.f32x2 %0, %1, %2;" : "=d"(d) : "d"(a), "d"(b));
    return d;
}
__device__ __forceinline__ double add2(double a, double b) {
    double d;
    asm("add.rn.f32x2 %0, %1, %2;" : "=d"(d) : "d"(a), "d"(b));
    return d;
}
__device__ __forceinline__ float2 unpack2(double d) {
    float2 r;
    asm("mov.b64 {%0, %1}, %2;" : "=f"(r.x), "=f"(r.y) : "d"(d));
    return r;
}
__device__ __forceinline__ void pack_row(float4 v, float scale, double* dst) {
    dst[0] = pack2(v.x * scale, v.y * scale);
    dst[1] = pack2(v.z * scale, v.w * scale);
}
__device__ __forceinline__ float pdot16(const double2 q0, const double2 q1,
                                        const double2 q2, const double2 q3,
                                        const double* w, double bias) {
    double a = fma2(q0.x, w[0], bias);
    a = fma2(q0.y, w[1], a);
    a = fma2(q1.x, w[2], a);
    a = fma2(q1.y, w[3], a);
    double b = mul2(q2.x, w[4]);
    b = fma2(q2.y, w[5], b);
    b = fma2(q3.x, w[6], b);
    b = fma2(q3.y, w[7], b);
    const float2 u = unpack2(add2(a, b));
    return u.x + u.y;
}

#define PAIR_BAR(wid4) asm volatile("bar.sync %0, 64;" :: "r"(1 + (wid4)) : "memory")

__global__ __launch_bounds__(THREADS, 1)
void gru_fused(const float* __restrict__ x,
               const float* __restrict__ w_ih,
               const float* __restrict__ w_hh,
               const float* __restrict__ b_ih,
               const float* __restrict__ b_hh,
               const float* __restrict__ fc_w,
               const float* __restrict__ fc_b,
               float* __restrict__ out) {
    // x stages: 3 x 32 rows x (16+1 pad) float4 = 26112 B
    __shared__ float4 sx[XBUFS][ROWS][17];
    // gate buffer: 2 stages x 4 steps x (32 rows * 4 lanes) float4 = 16384 B
    __shared__ float4 sg[2][SSTEPS][ROWS * 4];

    const int tid  = threadIdx.x;
    const int wid  = tid >> 5;
    const int wid4 = wid & 3;
    const int b0   = blockIdx.x * ROWS;

    if (wid >= 4) {
        // ================= PRODUCER warp (wid 4..7) =================
        const int ptid  = tid - 128;
        const int prow  = ptid >> 2;      // 0..31 (rows pwarp*8..pwarp*8+7)
        const int pj    = ptid & 3;
        const int pwarp = wid - 4;
        const int lane  = ptid & 31;

        // packed input weights; r/z pre-halved (sigmoid->tanh fold)
        const float4* W = (const float4*)w_ih;
        double wrP[8], wzP[8], wnP[8];
#pragma unroll
        for (int q = 0; q < 4; q++) {
            pack_row(__ldg(&W[(pj)     * 4 + q]), 0.5f, &wrP[q * 2]);
            pack_row(__ldg(&W[(4 + pj) * 4 + q]), 0.5f, &wzP[q * 2]);
            pack_row(__ldg(&W[(8 + pj) * 4 + q]), 1.0f, &wnP[q * 2]);
        }
        const double biasR = pack2(0.5f * (__ldg(&b_ih[pj])     + __ldg(&b_hh[pj])),     0.0f);
        const double biasZ = pack2(0.5f * (__ldg(&b_ih[4 + pj]) + __ldg(&b_hh[4 + pj])), 0.0f);
        const double biasN = pack2(__ldg(&b_ih[8 + pj]), 0.0f);

        // each producer warp stages x for ITS 8 rows: 8 rows x 16 float4 = 128 chunks
        const float4* xbase = (const float4*)x;
        auto issue_stage = [&](int s, int buf) {
#pragma unroll
            for (int k = 0; k < 4; k++) {
                const int c    = lane + k * 32;           // 0..127
                const int crow = pwarp * 8 + (c >> 4);
                const int cidx = c & 15;
                const float4* src = xbase + ((size_t)(b0 + crow) * GT + s * SSTEPS) * 4 + cidx;
                cp_async16(&sx[buf][crow][cidx], src);
            }
            cp_async_commit();
        };

        auto produce = [&](int s) {
            const double2* rx2 = (const double2*)&sx[s % XBUFS][prow][0];
            float4* gp = &sg[s & 1][0][prow * 4 + pj];
#pragma unroll
            for (int u = 0; u < SSTEPS; u++) {
                const double2 q0 = rx2[u * 4 + 0];
                const double2 q1 = rx2[u * 4 + 1];
                const double2 q2 = rx2[u * 4 + 2];
                const double2 q3 = rx2[u * 4 + 3];
                const float gr = pdot16(q0, q1, q2, q3, wrP, biasR);
                const float gz = pdot16(q0, q1, q2, q3, wzP, biasZ);
                const float gn = pdot16(q0, q1, q2, q3, wnP, biasN);
                gp[u * ROWS * 4] = make_float4(gr, gz, gn, 0.0f);
            }
        };

        // prologue: fill 3 x-buffers, produce gates[0]
        issue_stage(0, 0);
        issue_stage(1, 1);
        issue_stage(2, 2);
        asm volatile("cp.async.wait_group 2;\n" ::: "memory");
        __syncwarp();
        produce(0);

        for (int s = 0; s < NSTAGE; s++) {
            PAIR_BAR(wid4);   // gates[s] handed to scan; gates[s+1] buffer free
            if (s + 1 < NSTAGE) {
                if (s + 1 == NSTAGE - 1) {
                    // FINAL stage: its x-group is the newest pending one;
                    // wait_group 1 would NOT wait for it. Must drain fully.
                    asm volatile("cp.async.wait_group 0;\n" ::: "memory");
                } else {
                    asm volatile("cp.async.wait_group 1;\n" ::: "memory");
                }
                __syncwarp();
                produce(s + 1);
            }
            if (s + 3 < NSTAGE) {
                issue_stage(s + 3, (s + 3) % XBUFS);
            }
        }
    } else {
        // ================= SCAN warp (wid 0..3) =================
        const int srow = tid >> 2;
        const int j    = tid & 3;
        const int b    = b0 + srow;

        // hidden-side weights, pre-halved
        const float4* Wh = (const float4*)w_hh;
        float4 whr = __ldg(&Wh[j]);
        float4 whz = __ldg(&Wh[4 + j]);
        float4 whn = __ldg(&Wh[8 + j]);
        whr.x *= 0.5f; whr.y *= 0.5f; whr.z *= 0.5f; whr.w *= 0.5f;
        whz.x *= 0.5f; whz.y *= 0.5f; whz.z *= 0.5f; whz.w *= 0.5f;
        whn.x *= 0.5f; whn.y *= 0.5f; whn.z *= 0.5f; whn.w *= 0.5f;
        const float bhnh = 0.5f * __ldg(&b_hh[8 + j]);

        float h0 = 0.f, h1 = 0.f, h2 = 0.f, h3 = 0.f;
        float hhalf = 0.f;

        const float4* gbase = &sg[0][0][srow * 4 + j];

        for (int s = 0; s < NSTAGE; s++) {
            PAIR_BAR(wid4);   // gates[s] ready (producer's STS drained by BAR)
            const float4* gp = gbase + (s & 1) * (SSTEPS * ROWS * 4);
#pragma unroll
            for (int u = 0; u < SSTEPS; u++) {
                const float4 g = gp[u * ROWS * 4];   // (gr, gz, gn, 0)

                float ar = fmaf(h0, whr.x, g.x); ar = fmaf(h1, whr.y, ar);
                float cr = h2 * whr.z;           cr = fmaf(h3, whr.w, cr);
                const float arg_r = ar + cr;

                float az = fmaf(h0, whz.x, g.y); az = fmaf(h1, whz.y, az);
                float cz = h2 * whz.z;           cz = fmaf(h3, whz.w, cz);
                const float arg_z = az + cz;

                float an = fmaf(h0, whn.x, bhnh); an = fmaf(h1, whn.y, an);
                float cn = h2 * whn.z;            cn = fmaf(h3, whn.w, cn);
                const float ghn_h = an + cn;      // 0.5*(h.w_hh_n + b_hh_n)

                const float tr = tanh_fast(arg_r);
                const float tz = tanh_fast(arg_z);

                const float gnp  = g.z + ghn_h;
                const float narg = fmaf(tr, ghn_h, gnp);
                const float n    = tanh_fast(narg);

                const float dd = fmaf(n, -0.5f, hhalf);   // 0.5*(h_own - n)
                const float nt = n + dd;
                const float hn = fmaf(tz, dd, nt);

                hhalf = 0.5f * hn;
                h0 = __shfl_sync(0xffffffffu, hn, 0, 4);
                h1 = __shfl_sync(0xffffffffu, hn, 1, 4);
                h2 = __shfl_sync(0xffffffffu, hn, 2, 4);
                h3 = __shfl_sync(0xffffffffu, hn, 3, 4);
            }
        }

        if (j == 0) {
            const float fw0 = __ldg(&fc_w[0]), fw1 = __ldg(&fc_w[1]);
            const float fw2 = __ldg(&fc_w[2]), fw3 = __ldg(&fc_w[3]);
            out[b] = (h0 * fw0 + h1 * fw1) + (h2 * fw2 + h3 * fw3) + __ldg(&fc_b[0]);
        }
    }
}

extern "C" void kernel_launch(void* const* d_in, const int* in_sizes, int n_in,
                              void* d_out, int out_size) {
    const float* x    = (const float*)d_in[0];
    const float* w_ih = (const float*)d_in[1];
    const float* w_hh = (const float*)d_in[2];
    const float* b_ih = (const float*)d_in[3];
    const float* b_hh = (const float*)d_in[4];
    const float* fc_w = (const float*)d_in[5];
    const float* fc_b = (const float*)d_in[6];
    float* out = (float*)d_out;

    const int B = out_size;          // 4096
    const int blocks = B / ROWS;     // 128

    gru_fused<<<blocks, THREADS>>>(x, w_ih, w_hh, b_ih, b_hh, fc_w, fc_b, out);
}